// round 15
// baseline (speedup 1.0000x reference)
#include <cuda_runtime.h>
#include <cstdint>

#define BATCH  16
#define MAXLEN 128
#define NTOK   (BATCH * MAXLEN)   // 2048
#define VOCAB  32128
#define V4     (VOCAB / 4)        // 8032
#define V4H    (V4 / 2)           // 4016 float4s per half
#define EMB    768
#define EMB4   (EMB / 4)          // 192

// Cross-block combine scratch. Zero-initialized at module load; every kernel
// invocation self-cleans (finisher resets both words), so CUDA-graph replays
// see the same initial state — deterministic.
__device__ unsigned long long g_key[NTOK];
__device__ int                g_ticket[NTOK];

// monotone f32 -> u32 map: a > b  <=>  monotone(a) > monotone(b)
__device__ __forceinline__ unsigned monotone_f32(float f) {
    unsigned u = __float_as_uint(f);
    return (u & 0x80000000u) ? ~u : (u | 0x80000000u);
}

// ---------------------------------------------------------------------------
// Bit-exact replication of:
//   coord = jnp.linspace(-1, 1, size)[h]
//     JAX linspace (num>1): s = iota(f32 h)/f32(div); out = start*(1-s)+stop*s,
//     endpoint appended exactly as `stop`.
//   ix = ((coord + 1.0)*size - 1.0)/2.0 ;  round half-even ; clip [0, size-1]
// All ops forced to un-fused f32. (EMB column map is provably identity —
// validated by the rel_err=0 scalar-path runs — so only the vocab row uses
// this.)
// ---------------------------------------------------------------------------
__device__ __forceinline__ int nearest_idx_rep(int h, int size) {
    float coord;
    if (h == size - 1) {
        coord = 1.0f;                                     // endpoint set to stop
    } else {
        float s = __fdiv_rn((float)h, (float)(size - 1)); // iota/div
        float t = __fsub_rn(1.0f, s);                     // (1 - step)
        float a = __fmul_rn(-1.0f, t);                    // start*(1-step)
        coord   = __fadd_rn(a, s);                        // + stop*step
    }
    float u1 = __fadd_rn(coord, 1.0f);
    float u2 = __fmul_rn(u1, (float)size);
    float u3 = __fsub_rn(u2, 1.0f);
    float ix = __fdiv_rn(u3, 2.0f);
    float r  = rintf(ix);                                 // round half-to-even
    r = fminf(fmaxf(r, 0.0f), (float)(size - 1));
    return (int)r;
}

// ---------------------------------------------------------------------------
// Split-vocab mega-kernel: 4096 blocks, 2 blocks per token (half vocab each).
//   - masked token (mask[tok]==0): half 1 exits; half 0 does rb-only gather.
//   - live token: each half streams V/2 of (logits+gumbel), block-reduces
//     (max, min-idx), publishes one 64-bit key via atomicMax
//     (monotone(val)<<32 | ~idx  ==> max val, min idx on ties = jnp.argmax
//     first-occurrence). Ticket elects the 2nd-finishing block as finisher;
//     it decodes the global argmax, self-cleans scratch, then runs passage
//     bookkeeping + gather. Non-finishers exit (no redundant phase 2/3).
// Passage bookkeeping (per batch, mask/psg rows L2-hot):
//   psg_r    = roll(psg_ids, 1) with BOS=1
//   extr[k]  = (1 - mask[L-1-k]) * psg_r[k]
//   trunc[k] = extr[(k - sum(mask)) mod L]
//   flag[k]  = any_{i<=k} trunc[i] != 0  -> rb = flag[j] ? trunc[j] : -1
// Output: out[tok,:] = (ra>=0 ? WE[ra,:] : 0) + (rb>=0 ? WE[rb,:] : 0)
// ---------------------------------------------------------------------------
__global__ __launch_bounds__(256, 8) void k_all(
    const float4* __restrict__ lg, const float4* __restrict__ gm,
    const int* __restrict__ mask, const int* __restrict__ psg,
    const float4* __restrict__ we4, float4* __restrict__ out4)
{
    const int bid  = blockIdx.x;
    const int tok  = bid >> 1;
    const int half = bid & 1;
    const int tid  = threadIdx.x;

    __shared__ int   s_mask[MAXLEN];
    __shared__ int   s_extr[MAXLEN];
    __shared__ int   s_red[4];
    __shared__ int   s_rb, s_ra, s_fin;
    __shared__ float sv[8];
    __shared__ int   si[8];

    const int mj = __ldg(&mask[tok]);

    if (mj) {
        // ---- phase 1: stream this half's vocab slice ----
        const float4* L = lg + (size_t)tok * V4 + half * V4H;
        const float4* G = gm + (size_t)tok * V4 + half * V4H;
        const int idx0  = half * (V4H << 2);   // global vocab index of slice

        float best = -3.402823466e38f;
        int   bi   = 0;

        #pragma unroll 4
        for (int i = tid; i < V4H; i += 256) {
            float4 a = __ldcs(&L[i]);
            float4 c = __ldcs(&G[i]);
            float v0 = __fadd_rn(a.x, c.x);
            float v1 = __fadd_rn(a.y, c.y);
            float v2 = __fadd_rn(a.z, c.z);
            float v3 = __fadd_rn(a.w, c.w);
            int base = idx0 + (i << 2);
            // per-thread indices strictly increase -> '>' keeps first occurrence
            if (v0 > best) { best = v0; bi = base;     }
            if (v1 > best) { best = v1; bi = base + 1; }
            if (v2 > best) { best = v2; bi = base + 2; }
            if (v3 > best) { best = v3; bi = base + 3; }
        }

        // block reduce: (maxval, min-index-on-tie)
        #pragma unroll
        for (int o = 16; o > 0; o >>= 1) {
            float ov = __shfl_down_sync(0xffffffffu, best, o);
            int   oi = __shfl_down_sync(0xffffffffu, bi,   o);
            if (ov > best || (ov == best && oi < bi)) { best = ov; bi = oi; }
        }
        if ((tid & 31) == 0) { sv[tid >> 5] = best; si[tid >> 5] = bi; }
        __syncthreads();

        if (tid == 0) {
            best = sv[0]; bi = si[0];
            #pragma unroll
            for (int w = 1; w < 8; w++) {
                if (sv[w] > best || (sv[w] == best && si[w] < bi)) {
                    best = sv[w]; bi = si[w];
                }
            }
            unsigned long long key =
                ((unsigned long long)monotone_f32(best) << 32) |
                (unsigned)(~(unsigned)bi);
            atomicMax(&g_key[tok], key);
            __threadfence();
            int old = atomicAdd(&g_ticket[tok], 1);
            s_fin = (old == 1);                 // 2nd finisher owns the epilogue
        }
        __syncthreads();
        if (!s_fin) return;

        if (tid == 0) {
            // read combined key (atomic read from L2; no-op max)
            unsigned long long kk = atomicMax(&g_key[tok], 0ULL);
            // self-clean for the next graph replay
            atomicExch(&g_key[tok], 0ULL);
            atomicExch(&g_ticket[tok], 0);
            int bi_g = (int)(~(unsigned)(kk & 0xFFFFFFFFull));
            s_ra = nearest_idx_rep(bi_g, VOCAB);
        }
    } else {
        if (half) return;                       // dead token: one block suffices
        if (tid == 0) s_ra = -1;
    }

    // ---- phase 2: passage bookkeeping (finisher / dead-half0 only) ----
    const int b = tok >> 7;             // batch
    const int j = tok & (MAXLEN - 1);   // position within batch
    int m = 0, pj = 0;
    if (tid < MAXLEN) {
        m  = __ldg(&mask[b * MAXLEN + tid]);
        pj = (tid == 0) ? 1 : __ldg(&psg[b * MAXLEN + tid - 1]);
        s_mask[tid] = m;
    }
    __syncthreads();

    if (tid < MAXLEN) {
        s_extr[tid] = (1 - s_mask[MAXLEN - 1 - tid]) * pj;
        unsigned wsum = __reduce_add_sync(0xffffffffu, (unsigned)m);
        if ((tid & 31) == 0) s_red[tid >> 5] = (int)wsum;
    }
    __syncthreads();

    if (tid < MAXLEN) {
        int shifts = s_red[0] + s_red[1] + s_red[2] + s_red[3];
        int pos    = (tid - shifts + MAXLEN) & (MAXLEN - 1);
        int tr     = s_extr[pos];
        if (tid == j) s_rb = tr;                 // provisional: trunc[j]
        int key = (tr != 0) ? tid : MAXLEN;
        unsigned wmin = __reduce_min_sync(0xffffffffu, (unsigned)key);
        if ((tid & 31) == 0) s_red[tid >> 5] = (int)wmin;
    }
    __syncthreads();

    if (tid == 0) {
        int firstnz = min(min(s_red[0], s_red[1]), min(s_red[2], s_red[3]));
        if (j < firstnz) s_rb = -1;              // leading zeros -> no embed
    }
    __syncthreads();

    // ---- phase 3: float4 dual gather + store ----
    const int ra = s_ra;
    const int rb = s_rb;

    if (tid < EMB4) {
        float4 v = make_float4(0.f, 0.f, 0.f, 0.f);
        if (ra >= 0) v = __ldg(&we4[(size_t)ra * EMB4 + tid]);
        if (rb >= 0) {
            float4 w = __ldg(&we4[(size_t)rb * EMB4 + tid]);
            v.x = __fadd_rn(v.x, w.x);
            v.y = __fadd_rn(v.y, w.y);
            v.z = __fadd_rn(v.z, w.z);
            v.w = __fadd_rn(v.w, w.w);
        }
        out4[(size_t)tok * EMB4 + tid] = v;
    }
}

// ---------------------------------------------------------------------------
// Entry point. Inputs (metadata order):
//   0: logits           f32 [16,128,32128]
//   1: rwrt_attn_mask   i32 [16,128]
//   2: psg_input_ids    i32 [16,128]
//   3: word_embeddings  f32 [32128,768]
//   4: gumbel_noise     f32 [16,128,32128]
// Output: f32 [16,128,768]
// ---------------------------------------------------------------------------
extern "C" void kernel_launch(void* const* d_in, const int* in_sizes, int n_in,
                              void* d_out, int out_size)
{
    const float* logits = (const float*)d_in[0];
    const int*   mask   = (const int*)  d_in[1];
    const int*   psg    = (const int*)  d_in[2];
    const float* we     = (const float*)d_in[3];
    const float* gum    = (const float*)d_in[4];

    k_all<<<NTOK * 2, 256>>>((const float4*)logits, (const float4*)gum,
                             mask, psg, (const float4*)we, (float4*)d_out);
}

// round 16
// speedup vs baseline: 1.0371x; 1.0371x over previous
#include <cuda_runtime.h>
#include <cstdint>

#define BATCH  16
#define MAXLEN 128
#define NTOK   (BATCH * MAXLEN)   // 2048
#define VOCAB  32128
#define V4     (VOCAB / 4)        // 8032
#define EMB    768
#define EMB4   (EMB / 4)          // 192
#define BT     128                // threads per block
#define NWARP  (BT / 32)          // 4

// ---------------------------------------------------------------------------
// Bit-exact replication of:
//   coord = jnp.linspace(-1, 1, size)[h]
//     JAX linspace (num>1): s = iota(f32 h)/f32(div); out = start*(1-s)+stop*s,
//     endpoint appended exactly as `stop`.
//   ix = ((coord + 1.0)*size - 1.0)/2.0 ;  round half-even ; clip [0, size-1]
// All ops forced to un-fused f32. (EMB column map is provably identity —
// validated by the rel_err=0 scalar-path runs — so only the vocab row uses
// this.)
// ---------------------------------------------------------------------------
__device__ __forceinline__ int nearest_idx_rep(int h, int size) {
    float coord;
    if (h == size - 1) {
        coord = 1.0f;                                     // endpoint set to stop
    } else {
        float s = __fdiv_rn((float)h, (float)(size - 1)); // iota/div
        float t = __fsub_rn(1.0f, s);                     // (1 - step)
        float a = __fmul_rn(-1.0f, t);                    // start*(1-step)
        coord   = __fadd_rn(a, s);                        // + stop*step
    }
    float u1 = __fadd_rn(coord, 1.0f);
    float u2 = __fmul_rn(u1, (float)size);
    float u3 = __fsub_rn(u2, 1.0f);
    float ix = __fdiv_rn(u3, 2.0f);
    float r  = rintf(ix);                                 // round half-to-even
    r = fminf(fmaxf(r, 0.0f), (float)(size - 1));
    return (int)r;
}

// ---------------------------------------------------------------------------
// Single mega-kernel, SINGLE-WAVE config: one block per token, 2048 blocks of
// 128 threads, __launch_bounds__(128, 16) -> 32 regs, 16 blocks/SM, 64
// warps/SM (HW max). Capacity 148*16 = 2368 >= 2048: the ENTIRE grid is
// resident in one wave — no wave quantization, no ragged tail drain. Same
// per-SM warp count / MLP as the 256-thread occ-8 config that measured
// 6.0-6.2 TB/s, but with zero scheduling raggedness.
//
// Masked tokens (mask[tok]==0) skip the argmax stream entirely (their
// inputs_embeds row is multiplied by zero in the reference; `hot` feeds
// nothing else). ~25% of the 526 MB stream is dead work.
//
// Phase 1 (live tokens): first-occurrence argmax over V of (logits+gumbel),
//   pure HBM stream, evict-first so WE rows stay L2-resident.
// Phase 2: per-batch passage bookkeeping (mask/psg rows L2-hot):
//   psg_r    = roll(psg_ids, 1) with BOS=1
//   extr[k]  = (1 - mask[L-1-k]) * psg_r[k]
//   trunc[k] = extr[(k - sum(mask)) mod L]
//   flag[k]  = any_{i<=k} trunc[i] != 0  -> rb = flag[j] ? trunc[j] : -1
// Phase 3: ra = mask[j] ? nearest_idx(argmax) : -1, float4 dual gather:
//   out[tok,e] = (ra>=0 ? WE[ra,e] : 0) + (rb>=0 ? WE[rb,e] : 0)
// ---------------------------------------------------------------------------
__global__ __launch_bounds__(BT, 16) void k_all(
    const float4* __restrict__ lg, const float4* __restrict__ gm,
    const int* __restrict__ mask, const int* __restrict__ psg,
    const float4* __restrict__ we4, float4* __restrict__ out4)
{
    const int tok = blockIdx.x;
    const int tid = threadIdx.x;

    __shared__ int   s_mask[MAXLEN];
    __shared__ int   s_extr[MAXLEN];
    __shared__ int   s_red[NWARP];
    __shared__ int   s_rb;
    __shared__ float sv[NWARP];
    __shared__ int   si[NWARP];

    // block-uniform liveness check (single broadcast address, L2-hot)
    const int mj = __ldg(&mask[tok]);

    float best = -3.402823466e38f;
    int   bi   = 0;

    if (mj) {
        // ---- phase 1: streaming argmax (live tokens only) ----
        const float4* L = lg + (size_t)tok * V4;
        const float4* G = gm + (size_t)tok * V4;

        #pragma unroll 4
        for (int i = tid; i < V4; i += BT) {
            float4 a = __ldcs(&L[i]);
            float4 c = __ldcs(&G[i]);
            float v0 = __fadd_rn(a.x, c.x);
            float v1 = __fadd_rn(a.y, c.y);
            float v2 = __fadd_rn(a.z, c.z);
            float v3 = __fadd_rn(a.w, c.w);
            int base = i << 2;
            // per-thread indices strictly increase -> '>' keeps first occurrence
            if (v0 > best) { best = v0; bi = base;     }
            if (v1 > best) { best = v1; bi = base + 1; }
            if (v2 > best) { best = v2; bi = base + 2; }
            if (v3 > best) { best = v3; bi = base + 3; }
        }
    }

    // ---- phase 2: issue tiny L2-hot loads, hide under the shuffle reduce ----
    const int b = tok >> 7;             // batch
    const int j = tok & (MAXLEN - 1);   // position within batch
    int m  = __ldg(&mask[b * MAXLEN + tid]);
    int pj = (tid == 0) ? 1 : __ldg(&psg[b * MAXLEN + tid - 1]);

    // (maxval, min-index-on-tie) semilattice reduce == jnp.argmax semantics
    #pragma unroll
    for (int o = 16; o > 0; o >>= 1) {
        float ov = __shfl_down_sync(0xffffffffu, best, o);
        int   oi = __shfl_down_sync(0xffffffffu, bi,   o);
        if (ov > best || (ov == best && oi < bi)) { best = ov; bi = oi; }
    }
    if ((tid & 31) == 0) { sv[tid >> 5] = best; si[tid >> 5] = bi; }
    s_mask[tid] = m;
    __syncthreads();

    {
        s_extr[tid] = (1 - s_mask[MAXLEN - 1 - tid]) * pj;
        unsigned wsum = __reduce_add_sync(0xffffffffu, (unsigned)m);
        if ((tid & 31) == 0) s_red[tid >> 5] = (int)wsum;
    }
    __syncthreads();

    {
        int shifts = s_red[0] + s_red[1] + s_red[2] + s_red[3];
        int pos    = (tid - shifts + MAXLEN) & (MAXLEN - 1);
        int tr     = s_extr[pos];
        if (tid == j) s_rb = tr;                 // provisional: trunc[j]
        int key = (tr != 0) ? tid : MAXLEN;
        unsigned wmin = __reduce_min_sync(0xffffffffu, (unsigned)key);
        if ((tid & 31) == 0) s_red[tid >> 5] = (int)wmin;
    }
    __syncthreads();

    if (tid == 0) {
        int firstnz = min(min(s_red[0], s_red[1]), min(s_red[2], s_red[3]));
        if (j < firstnz) s_rb = -1;              // leading zeros -> no embed
        // final argmax reduce across the 4 warps
        best = sv[0]; bi = si[0];
        #pragma unroll
        for (int w = 1; w < NWARP; w++) {
            if (sv[w] > best || (sv[w] == best && si[w] < bi)) {
                best = sv[w]; bi = si[w];
            }
        }
        // ra: grid_sample-nearest row for the argmax token (or -1 if masked)
        si[0] = mj ? nearest_idx_rep(bi, VOCAB) : -1;
    }
    __syncthreads();

    // ---- phase 3: float4 dual gather + store (WE rows 16B-aligned) ----
    const int ra = si[0];
    const int rb = s_rb;

    #pragma unroll
    for (int e = tid; e < EMB4; e += BT) {
        float4 v = make_float4(0.f, 0.f, 0.f, 0.f);
        if (ra >= 0) v = __ldg(&we4[(size_t)ra * EMB4 + e]);
        if (rb >= 0) {
            float4 w = __ldg(&we4[(size_t)rb * EMB4 + e]);
            v.x = __fadd_rn(v.x, w.x);
            v.y = __fadd_rn(v.y, w.y);
            v.z = __fadd_rn(v.z, w.z);
            v.w = __fadd_rn(v.w, w.w);
        }
        out4[(size_t)tok * EMB4 + e] = v;
    }
}

// ---------------------------------------------------------------------------
// Entry point. Inputs (metadata order):
//   0: logits           f32 [16,128,32128]
//   1: rwrt_attn_mask   i32 [16,128]
//   2: psg_input_ids    i32 [16,128]
//   3: word_embeddings  f32 [32128,768]
//   4: gumbel_noise     f32 [16,128,32128]
// Output: f32 [16,128,768]
// ---------------------------------------------------------------------------
extern "C" void kernel_launch(void* const* d_in, const int* in_sizes, int n_in,
                              void* d_out, int out_size)
{
    const float* logits = (const float*)d_in[0];
    const int*   mask   = (const int*)  d_in[1];
    const int*   psg    = (const int*)  d_in[2];
    const float* we     = (const float*)d_in[3];
    const float* gum    = (const float*)d_in[4];

    k_all<<<NTOK, BT>>>((const float4*)logits, (const float4*)gum,
                        mask, psg, (const float4*)we, (float4*)d_out);
}